// round 5
// baseline (speedup 1.0000x reference)
#include <cuda_runtime.h>
#include <cstdint>

// ---------------------------------------------------------------------------
// LinearAttention fused:
//   final[b] = M_b @ x[b] + b_out
//   M_b derived from ctx[b,h] = softmax(Wk@x) @ (Wv@x)^T  (32x32 per head)
// K1: per (batch, n-chunk) compute kv = Wkv@x tile-wise, accumulate
//     partial A[h][d][e] = sum_n exp(k_dn) v_en and S[h][d] = sum_n exp(k_dn)
// K2a: reduce partials -> ctx ; K2b: U = Wout_h @ ctx_h^T ; K2c: M = scale*U@Wq
// K3: final = M_b @ x + b_out
// ---------------------------------------------------------------------------

#define BATCH 16
#define CDIM 128
#define NSP 16384
#define NHEADS 4
#define DHEAD 32
#define NCHUNKS 32
#define CHUNK 512
#define SUBN 32
#define NSUB 16
#define WPITCH 260
#define KPITCH 36

__device__ float g_partA[BATCH * NCHUNKS * 128 * 32];  // [b][ch][hd][e]
__device__ float g_partS[BATCH * NCHUNKS * 128];       // [b][ch][hd]
__device__ float g_ctx[BATCH * 128 * 32];              // [b][hd][e]
__device__ float g_U[BATCH * 128 * 128];               // [b][o][hd]
__device__ float g_M[BATCH * 128 * 128];               // [b][o][c]

#define SM1_FLOATS (128 * WPITCH + 128 * SUBN + 2 * 128 * KPITCH)
#define SM3_FLOATS (128 * 132 + 128 * 128)

// ---------------------------------------------------------------------------
// K1: context partials. grid (NCHUNKS, BATCH), 256 threads.
// smem: wT[k][row] (256 kv rows of w_qkv, transposed), xs[c][col],
//       ke[hd][col] (exp of k logits), vsm[he][col] (v values)
// ---------------------------------------------------------------------------
__global__ __launch_bounds__(256, 1) void k1_ctx(const float* __restrict__ x,
                                                 const float* __restrict__ w_qkv) {
    extern __shared__ float sm[];
    float* wT  = sm;                   // [128 k][256 rows] pitch WPITCH
    float* xs  = wT + 128 * WPITCH;    // [128 c][SUBN]
    float* ke  = xs + 128 * SUBN;      // [128 hd][SUBN] pitch KPITCH
    float* vsm = ke + 128 * KPITCH;    // [128 he][SUBN] pitch KPITCH

    const int t  = threadIdx.x;
    const int b  = blockIdx.y;
    const int ch = blockIdx.x;
    const int n0 = ch * CHUNK;

    // Load W^T for kv rows (w_qkv rows 128..383). Thread t owns kv row t.
    {
        const float* wr = w_qkv + (size_t)(128 + t) * CDIM;
#pragma unroll
        for (int k4 = 0; k4 < CDIM; k4 += 4) {
            float4 wv = *(const float4*)(wr + k4);
            wT[(k4 + 0) * WPITCH + t] = wv.x;
            wT[(k4 + 1) * WPITCH + t] = wv.y;
            wT[(k4 + 2) * WPITCH + t] = wv.z;
            wT[(k4 + 3) * WPITCH + t] = wv.w;
        }
    }

    // A-phase ownership: thread -> (hd = t>>1, p = t&1), e in [p*16, p*16+16)
    const int hd = t >> 1;
    const int p  = t & 1;
    const int h  = hd >> 5;
    float Aacc[16];
#pragma unroll
    for (int i = 0; i < 16; i++) Aacc[i] = 0.f;
    float Sacc = 0.f;

    // GEMM ownership: thread -> rows tr*8..tr*8+7, cols tc*4..tc*4+3
    const int tr = t >> 3;
    const int tc = t & 7;

    const float* xb = x + (size_t)b * CDIM * NSP + n0;

    __syncthreads();

    for (int s = 0; s < NSUB; s++) {
        // ---- load x subtile (128 x 32) ----
#pragma unroll
        for (int i = 0; i < 4; i++) {
            int li = t + i * 256;           // 0..1023 float4 units
            int c  = li >> 3;
            int c4 = (li & 7) * 4;
            float4 v = *(const float4*)(xb + (size_t)c * NSP + s * SUBN + c4);
            *(float4*)(xs + c * SUBN + c4) = v;
        }
        __syncthreads();

        // ---- kv = Wkv @ x (256x32, K=128) ----
        float acc[8][4];
#pragma unroll
        for (int i = 0; i < 8; i++)
#pragma unroll
            for (int j = 0; j < 4; j++) acc[i][j] = 0.f;

#pragma unroll 4
        for (int k = 0; k < CDIM; k++) {
            float4 w0 = *(const float4*)(wT + k * WPITCH + tr * 8);
            float4 w1 = *(const float4*)(wT + k * WPITCH + tr * 8 + 4);
            float4 xv = *(const float4*)(xs + k * SUBN + tc * 4);
            float wv[8] = {w0.x, w0.y, w0.z, w0.w, w1.x, w1.y, w1.z, w1.w};
            float xf[4] = {xv.x, xv.y, xv.z, xv.w};
#pragma unroll
            for (int i = 0; i < 8; i++)
#pragma unroll
                for (int j = 0; j < 4; j++) acc[i][j] += wv[i] * xf[j];
        }

        // ---- write exp(k) / v tiles ----
        if (tr < 16) {
#pragma unroll
            for (int i = 0; i < 8; i++) {
                int row = tr * 8 + i;
#pragma unroll
                for (int j = 0; j < 4; j++)
                    ke[row * KPITCH + tc * 4 + j] = __expf(acc[i][j]);
            }
        } else {
#pragma unroll
            for (int i = 0; i < 8; i++) {
                int row = (tr - 16) * 8 + i;
#pragma unroll
                for (int j = 0; j < 4; j++)
                    vsm[row * KPITCH + tc * 4 + j] = acc[i][j];
            }
        }
        __syncthreads();

        // ---- A[h][d][e] += ke[hd] . vsm[h*32+e], S[hd] += sum(ke[hd]) ----
#pragma unroll
        for (int c4 = 0; c4 < SUBN; c4 += 4) {
            float4 kv = *(const float4*)(ke + hd * KPITCH + c4);
            if (p == 0) Sacc += (kv.x + kv.y) + (kv.z + kv.w);
#pragma unroll
            for (int i = 0; i < 16; i++) {
                float4 vv = *(const float4*)(vsm + (h * DHEAD + p * 16 + i) * KPITCH + c4);
                Aacc[i] += kv.x * vv.x + kv.y * vv.y + kv.z * vv.z + kv.w * vv.w;
            }
        }
        __syncthreads();
    }

    // ---- write partials ----
    float* pa = g_partA + ((size_t)(b * NCHUNKS + ch) * 128 + hd) * 32 + p * 16;
#pragma unroll
    for (int i = 0; i < 16; i++) pa[i] = Aacc[i];
    if (p == 0) g_partS[(b * NCHUNKS + ch) * 128 + hd] = Sacc;
}

// ---------------------------------------------------------------------------
// K2a: reduce partials -> ctx[b][hd][e] = A/S. 65536 threads.
// ---------------------------------------------------------------------------
__global__ void k2_ctx() {
    int idx = blockIdx.x * blockDim.x + threadIdx.x;   // 0..65535
    int b  = idx >> 12;
    int r  = idx & 4095;
    int hd = r >> 5;
    int e  = r & 31;
    float sA = 0.f, sS = 0.f;
    for (int chn = 0; chn < NCHUNKS; chn++) {
        sA += g_partA[((size_t)(b * NCHUNKS + chn) * 128 + hd) * 32 + e];
        sS += g_partS[(b * NCHUNKS + chn) * 128 + hd];
    }
    g_ctx[idx] = sA / sS;
}

// ---------------------------------------------------------------------------
// K2b: U[b][o][hd] = sum_e w_out[o][h*32+e] * ctx[b][hd][e]. 262144 threads.
// ---------------------------------------------------------------------------
__global__ void k2_u(const float* __restrict__ w_out) {
    int idx = blockIdx.x * blockDim.x + threadIdx.x;   // 0..262143
    int b  = idx >> 14;
    int o  = (idx >> 7) & 127;
    int hd = idx & 127;
    int h  = hd >> 5;
    const float* wo = w_out + (size_t)o * 128 + h * 32;
    const float* cx = g_ctx + (size_t)b * 4096 + hd * 32;
    float acc = 0.f;
#pragma unroll
    for (int e = 0; e < 32; e++) acc += wo[e] * cx[e];
    g_U[idx] = acc;
}

// ---------------------------------------------------------------------------
// K2c: M[b][o][c] = scale * sum_hd U[b][o][hd] * w_qkv[hd][c]. 262144 threads.
// ---------------------------------------------------------------------------
__global__ void k2_m(const float* __restrict__ w_qkv) {
    int idx = blockIdx.x * blockDim.x + threadIdx.x;   // 0..262143
    int b = idx >> 14;
    int o = (idx >> 7) & 127;
    int c = idx & 127;
    const float* U = g_U + ((size_t)b * 128 + o) * 128;
    float acc = 0.f;
#pragma unroll 8
    for (int hd = 0; hd < 128; hd++)
        acc += U[hd] * w_qkv[(size_t)hd * CDIM + c];
    g_M[idx] = 0.17677669529663687f * acc;   // 1/sqrt(32)
}

// ---------------------------------------------------------------------------
// K3: final[b] = M_b @ x[b] + b_out. grid (128 tiles, BATCH), 256 threads.
// ---------------------------------------------------------------------------
__global__ __launch_bounds__(256, 1) void k3_out(const float* __restrict__ x,
                                                 const float* __restrict__ b_out,
                                                 float* __restrict__ out) {
    extern __shared__ float sm[];
    float* Ms = sm;              // [o][c] pitch 132
    float* xs = Ms + 128 * 132;  // [c][col] pitch 128

    const int t    = threadIdx.x;
    const int b    = blockIdx.y;
    const int tile = blockIdx.x;
    const int n0   = tile * 128;

    const float* Mg = g_M + (size_t)b * 16384;
#pragma unroll
    for (int i = 0; i < 16; i++) {
        int li = t + i * 256;        // 0..4095 float4 units
        int o  = li >> 5;
        int c4 = (li & 31) * 4;
        float4 v = *(const float4*)(Mg + (size_t)o * 128 + c4);
        *(float4*)(Ms + o * 132 + c4) = v;
    }
    const float* xb = x + (size_t)b * CDIM * NSP + n0;
#pragma unroll
    for (int i = 0; i < 16; i++) {
        int li = t + i * 256;
        int c  = li >> 5;
        int c4 = (li & 31) * 4;
        float4 v = *(const float4*)(xb + (size_t)c * NSP + c4);
        *(float4*)(xs + c * 128 + c4) = v;
    }
    __syncthreads();

    const int ty = t >> 4;   // rows ty*8..+7
    const int tx = t & 15;   // cols tx*8..+7
    float acc[8][8];
#pragma unroll
    for (int i = 0; i < 8; i++)
#pragma unroll
        for (int j = 0; j < 8; j++) acc[i][j] = 0.f;

    for (int c4 = 0; c4 < CDIM; c4 += 4) {
        float mvf[8][4];
#pragma unroll
        for (int i = 0; i < 8; i++) {
            float4 q = *(const float4*)(Ms + (ty * 8 + i) * 132 + c4);
            mvf[i][0] = q.x; mvf[i][1] = q.y; mvf[i][2] = q.z; mvf[i][3] = q.w;
        }
#pragma unroll
        for (int cc = 0; cc < 4; cc++) {
            float4 x0 = *(const float4*)(xs + (c4 + cc) * 128 + tx * 8);
            float4 x1 = *(const float4*)(xs + (c4 + cc) * 128 + tx * 8 + 4);
            float xf[8] = {x0.x, x0.y, x0.z, x0.w, x1.x, x1.y, x1.z, x1.w};
#pragma unroll
            for (int i = 0; i < 8; i++)
#pragma unroll
                for (int j = 0; j < 8; j++) acc[i][j] += mvf[i][cc] * xf[j];
        }
    }

#pragma unroll
    for (int i = 0; i < 8; i++) {
        int o = ty * 8 + i;
        float bo = b_out[o];
        float* og = out + ((size_t)b * CDIM + o) * NSP + n0 + tx * 8;
        float4 r0 = {acc[i][0] + bo, acc[i][1] + bo, acc[i][2] + bo, acc[i][3] + bo};
        float4 r1 = {acc[i][4] + bo, acc[i][5] + bo, acc[i][6] + bo, acc[i][7] + bo};
        *(float4*)og = r0;
        *(float4*)(og + 4) = r1;
    }
}

// ---------------------------------------------------------------------------
extern "C" void kernel_launch(void* const* d_in, const int* in_sizes, int n_in,
                              void* d_out, int out_size) {
    const float* x     = (const float*)d_in[0];
    const float* w_qkv = (const float*)d_in[1];
    const float* w_out = (const float*)d_in[2];
    const float* b_out = (const float*)d_in[3];
    float* out = (float*)d_out;

    cudaFuncSetAttribute(k1_ctx, cudaFuncAttributeMaxDynamicSharedMemorySize,
                         SM1_FLOATS * sizeof(float));
    cudaFuncSetAttribute(k3_out, cudaFuncAttributeMaxDynamicSharedMemorySize,
                         SM3_FLOATS * sizeof(float));

    k1_ctx<<<dim3(NCHUNKS, BATCH), 256, SM1_FLOATS * sizeof(float)>>>(x, w_qkv);
    k2_ctx<<<256, 256>>>();
    k2_u<<<1024, 256>>>(w_out);
    k2_m<<<1024, 256>>>(w_qkv);
    k3_out<<<dim3(NSP / 128, BATCH), 256, SM3_FLOATS * sizeof(float)>>>(x, b_out, out);
}

// round 8
// speedup vs baseline: 1.0913x; 1.0913x over previous
#include <cuda_runtime.h>
#include <cuda_bf16.h>
#include <cstdint>

// ---------------------------------------------------------------------------
// LinearAttention fused:
//   final[b] = M_b @ x[b] + b_out
//   M_b derived from ctx[b,h] = softmax(Wk@x) @ (Wv@x)^T  (32x32 per head)
// K1 (FFMA, unchanged): context partials.
// K2a/b/c (unchanged): reduce -> ctx -> U -> M.
// K3 (HMMA mma.sync): final = M_b @ x + b_out, bf16 3-term split, fp32 acc.
//   (tcgen05 is unavailable: harness compiles via compute_103 PTX, which
//    rejects all arch-'a' instructions. mma.sync.m16n8k16 is baseline PTX.)
// ---------------------------------------------------------------------------

#define BATCH 16
#define CDIM 128
#define NSP 16384
#define NHEADS 4
#define DHEAD 32
#define NCHUNKS 32
#define CHUNK 512
#define SUBN 32
#define NSUB 16
#define WPITCH 260
#define KPITCH 36

__device__ float g_partA[BATCH * NCHUNKS * 128 * 32];  // [b][ch][hd][e]
__device__ float g_partS[BATCH * NCHUNKS * 128];       // [b][ch][hd]
__device__ float g_ctx[BATCH * 128 * 32];              // [b][hd][e]
__device__ float g_U[BATCH * 128 * 128];               // [b][o][hd]
__device__ float g_M[BATCH * 128 * 128];               // [b][o][c]

#define SM1_FLOATS (128 * WPITCH + 128 * SUBN + 2 * 128 * KPITCH)

// ---------------------------------------------------------------------------
// K1: context partials. grid (NCHUNKS, BATCH), 256 threads.  (unchanged)
// ---------------------------------------------------------------------------
__global__ __launch_bounds__(256, 1) void k1_ctx(const float* __restrict__ x,
                                                 const float* __restrict__ w_qkv) {
    extern __shared__ float sm[];
    float* wT  = sm;                   // [128 k][256 rows] pitch WPITCH
    float* xs  = wT + 128 * WPITCH;    // [128 c][SUBN]
    float* ke  = xs + 128 * SUBN;      // [128 hd][SUBN] pitch KPITCH
    float* vsm = ke + 128 * KPITCH;    // [128 he][SUBN] pitch KPITCH

    const int t  = threadIdx.x;
    const int b  = blockIdx.y;
    const int ch = blockIdx.x;
    const int n0 = ch * CHUNK;

    {
        const float* wr = w_qkv + (size_t)(128 + t) * CDIM;
#pragma unroll
        for (int k4 = 0; k4 < CDIM; k4 += 4) {
            float4 wv = *(const float4*)(wr + k4);
            wT[(k4 + 0) * WPITCH + t] = wv.x;
            wT[(k4 + 1) * WPITCH + t] = wv.y;
            wT[(k4 + 2) * WPITCH + t] = wv.z;
            wT[(k4 + 3) * WPITCH + t] = wv.w;
        }
    }

    const int hd = t >> 1;
    const int p  = t & 1;
    const int h  = hd >> 5;
    float Aacc[16];
#pragma unroll
    for (int i = 0; i < 16; i++) Aacc[i] = 0.f;
    float Sacc = 0.f;

    const int tr = t >> 3;
    const int tc = t & 7;

    const float* xb = x + (size_t)b * CDIM * NSP + n0;

    __syncthreads();

    for (int s = 0; s < NSUB; s++) {
#pragma unroll
        for (int i = 0; i < 4; i++) {
            int li = t + i * 256;
            int c  = li >> 3;
            int c4 = (li & 7) * 4;
            float4 v = *(const float4*)(xb + (size_t)c * NSP + s * SUBN + c4);
            *(float4*)(xs + c * SUBN + c4) = v;
        }
        __syncthreads();

        float acc[8][4];
#pragma unroll
        for (int i = 0; i < 8; i++)
#pragma unroll
            for (int j = 0; j < 4; j++) acc[i][j] = 0.f;

#pragma unroll 4
        for (int k = 0; k < CDIM; k++) {
            float4 w0 = *(const float4*)(wT + k * WPITCH + tr * 8);
            float4 w1 = *(const float4*)(wT + k * WPITCH + tr * 8 + 4);
            float4 xv = *(const float4*)(xs + k * SUBN + tc * 4);
            float wv[8] = {w0.x, w0.y, w0.z, w0.w, w1.x, w1.y, w1.z, w1.w};
            float xf[4] = {xv.x, xv.y, xv.z, xv.w};
#pragma unroll
            for (int i = 0; i < 8; i++)
#pragma unroll
                for (int j = 0; j < 4; j++) acc[i][j] += wv[i] * xf[j];
        }

        if (tr < 16) {
#pragma unroll
            for (int i = 0; i < 8; i++) {
                int row = tr * 8 + i;
#pragma unroll
                for (int j = 0; j < 4; j++)
                    ke[row * KPITCH + tc * 4 + j] = __expf(acc[i][j]);
            }
        } else {
#pragma unroll
            for (int i = 0; i < 8; i++) {
                int row = (tr - 16) * 8 + i;
#pragma unroll
                for (int j = 0; j < 4; j++)
                    vsm[row * KPITCH + tc * 4 + j] = acc[i][j];
            }
        }
        __syncthreads();

#pragma unroll
        for (int c4 = 0; c4 < SUBN; c4 += 4) {
            float4 kv = *(const float4*)(ke + hd * KPITCH + c4);
            if (p == 0) Sacc += (kv.x + kv.y) + (kv.z + kv.w);
#pragma unroll
            for (int i = 0; i < 16; i++) {
                float4 vv = *(const float4*)(vsm + (h * DHEAD + p * 16 + i) * KPITCH + c4);
                Aacc[i] += kv.x * vv.x + kv.y * vv.y + kv.z * vv.z + kv.w * vv.w;
            }
        }
        __syncthreads();
    }

    float* pa = g_partA + ((size_t)(b * NCHUNKS + ch) * 128 + hd) * 32 + p * 16;
#pragma unroll
    for (int i = 0; i < 16; i++) pa[i] = Aacc[i];
    if (p == 0) g_partS[(b * NCHUNKS + ch) * 128 + hd] = Sacc;
}

// ---------------------------------------------------------------------------
// K2a: reduce partials -> ctx[b][hd][e] = A/S.
// ---------------------------------------------------------------------------
__global__ void k2_ctx() {
    int idx = blockIdx.x * blockDim.x + threadIdx.x;
    int b  = idx >> 12;
    int r  = idx & 4095;
    int hd = r >> 5;
    int e  = r & 31;
    float sA = 0.f, sS = 0.f;
    for (int chn = 0; chn < NCHUNKS; chn++) {
        sA += g_partA[((size_t)(b * NCHUNKS + chn) * 128 + hd) * 32 + e];
        sS += g_partS[(b * NCHUNKS + chn) * 128 + hd];
    }
    g_ctx[idx] = sA / sS;
}

// ---------------------------------------------------------------------------
// K2b: U[b][o][hd] = sum_e w_out[o][h*32+e] * ctx[b][hd][e].
// ---------------------------------------------------------------------------
__global__ void k2_u(const float* __restrict__ w_out) {
    int idx = blockIdx.x * blockDim.x + threadIdx.x;
    int b  = idx >> 14;
    int o  = (idx >> 7) & 127;
    int hd = idx & 127;
    int h  = hd >> 5;
    const float* wo = w_out + (size_t)o * 128 + h * 32;
    const float* cx = g_ctx + (size_t)b * 4096 + hd * 32;
    float acc = 0.f;
#pragma unroll
    for (int e = 0; e < 32; e++) acc += wo[e] * cx[e];
    g_U[idx] = acc;
}

// ---------------------------------------------------------------------------
// K2c: M[b][o][c] = scale * sum_hd U[b][o][hd] * w_qkv[hd][c].
// ---------------------------------------------------------------------------
__global__ void k2_m(const float* __restrict__ w_qkv) {
    int idx = blockIdx.x * blockDim.x + threadIdx.x;
    int b = idx >> 14;
    int o = (idx >> 7) & 127;
    int c = idx & 127;
    const float* U = g_U + ((size_t)b * 128 + o) * 128;
    float acc = 0.f;
#pragma unroll 8
    for (int hd = 0; hd < 128; hd++)
        acc += U[hd] * w_qkv[(size_t)hd * CDIM + c];
    g_M[idx] = 0.17677669529663687f * acc;   // 1/sqrt(32)
}

// ===========================================================================
// K3 (HMMA): final[b](128 x 16384) = M_b(128x128) @ x[b] + b_out.
// grid (128 n-tiles, BATCH), 256 threads (8 warps), 1 CTA = 128x128 out tile.
// bf16 3-term split: D = Ah@Bh + Ah@Bl + Al@Bh, fp32 register accumulation.
// smem layout: packed k-pairs, P[kk][row] as bf16x2 word, pitch 136 words
// (136 mod 32 = 8 -> fragment reads (136q + g) hit 32 distinct banks).
// ===========================================================================
#define K3_PITCH 136
#define K3_MAT_WORDS (64 * K3_PITCH)                 // 8704 words = 34816 B
#define K3_SMEM_BYTES (4 * K3_MAT_WORDS * 4)         // 139264 B

__device__ __forceinline__ uint32_t pack_bf16(__nv_bfloat16 a, __nv_bfloat16 b) {
    __nv_bfloat162 t2{a, b};
    return *(uint32_t*)&t2;
}
__device__ __forceinline__ void bf16_split(float v, __nv_bfloat16& h, __nv_bfloat16& l) {
    h = __float2bfloat16(v);
    l = __float2bfloat16(v - __bfloat162float(h));
}
__device__ __forceinline__ void mma16816(float* d, const uint32_t* a, const uint32_t* bf) {
    asm volatile(
        "mma.sync.aligned.m16n8k16.row.col.f32.bf16.bf16.f32 "
        "{%0,%1,%2,%3}, {%4,%5,%6,%7}, {%8,%9}, {%0,%1,%2,%3};"
        : "+f"(d[0]), "+f"(d[1]), "+f"(d[2]), "+f"(d[3])
        : "r"(a[0]), "r"(a[1]), "r"(a[2]), "r"(a[3]), "r"(bf[0]), "r"(bf[1]));
}

__global__ __launch_bounds__(256, 1) void k3_mm(const float* __restrict__ x,
                                                const float* __restrict__ b_out,
                                                float* __restrict__ out) {
    extern __shared__ uint32_t sm4[];
    uint32_t* A2h = sm4;
    uint32_t* A2l = sm4 + K3_MAT_WORDS;
    uint32_t* B2h = sm4 + 2 * K3_MAT_WORDS;
    uint32_t* B2l = sm4 + 3 * K3_MAT_WORDS;

    const int t   = threadIdx.x;
    const int wid = t >> 5;
    const int lane = t & 31;
    const int b   = blockIdx.y;
    const int n0  = blockIdx.x * 128;

    // ---- fill A = M_b [o][c]: pack k-pairs -> A2[kk=c/2][o] (STS.32) ----
    {
        const float* Mg = g_M + (size_t)b * 16384;
#pragma unroll
        for (int i = 0; i < 16; i++) {
            int li = t + i * 256;          // 4096 = 128 o x 32 c4-blocks
            int o  = li & 127;
            int c4 = (li >> 7) * 4;
            float4 v = *(const float4*)(Mg + (size_t)o * 128 + c4);
            __nv_bfloat16 h0, h1, h2, h3, l0, l1, l2, l3;
            bf16_split(v.x, h0, l0); bf16_split(v.y, h1, l1);
            bf16_split(v.z, h2, l2); bf16_split(v.w, h3, l3);
            int kk = c4 >> 1;
            A2h[kk * K3_PITCH + o]       = pack_bf16(h0, h1);
            A2h[(kk + 1) * K3_PITCH + o] = pack_bf16(h2, h3);
            A2l[kk * K3_PITCH + o]       = pack_bf16(l0, l1);
            A2l[(kk + 1) * K3_PITCH + o] = pack_bf16(l2, l3);
        }
    }

    // ---- fill B = x[c][n0..n0+127]: transpose-pack via STS.16 ----
    {
        const float* xb = x + (size_t)b * CDIM * NSP + n0;
        __nv_bfloat16* Bh16 = (__nv_bfloat16*)B2h;
        __nv_bfloat16* Bl16 = (__nv_bfloat16*)B2l;
#pragma unroll
        for (int i = 0; i < 16; i++) {
            int li = t + i * 256;          // 4096 = 128 c x 32 n4-blocks
            int c  = li >> 5;
            int n4 = (li & 31) * 4;
            float4 v = *(const float4*)(xb + (size_t)c * NSP + n4);
            int kk = c >> 1, par = c & 1;
            float vv[4] = {v.x, v.y, v.z, v.w};
#pragma unroll
            for (int j = 0; j < 4; j++) {
                __nv_bfloat16 h, l;
                bf16_split(vv[j], h, l);
                int widx = kk * K3_PITCH + n4 + j;
                Bh16[widx * 2 + par] = h;
                Bl16[widx * 2 + par] = l;
            }
        }
    }
    __syncthreads();

    // ---- warp tiles: 4 (M) x 2 (N) warps -> 32x64 each ----
    const int g = lane >> 2;       // row-in-group 0..7
    const int q = lane & 3;        // k-pair lane 0..3
    const int m0  = (wid >> 1) * 32;
    const int nb0 = (wid & 1) * 64;

    float acc[2][8][4];
#pragma unroll
    for (int f = 0; f < 2; f++)
#pragma unroll
        for (int nf = 0; nf < 8; nf++)
#pragma unroll
            for (int j = 0; j < 4; j++) acc[f][nf][j] = 0.f;

#pragma unroll
    for (int kt = 0; kt < 8; kt++) {
        const int k0 = kt * 8;
        uint32_t ah[2][4], al[2][4], bh[8][2], bl[8][2];
#pragma unroll
        for (int f = 0; f < 2; f++) {
            int r = m0 + f * 16 + g;
            ah[f][0] = A2h[(k0 + q) * K3_PITCH + r];
            ah[f][1] = A2h[(k0 + q) * K3_PITCH + r + 8];
            ah[f][2] = A2h[(k0 + q + 4) * K3_PITCH + r];
            ah[f][3] = A2h[(k0 + q + 4) * K3_PITCH + r + 8];
            al[f][0] = A2l[(k0 + q) * K3_PITCH + r];
            al[f][1] = A2l[(k0 + q) * K3_PITCH + r + 8];
            al[f][2] = A2l[(k0 + q + 4) * K3_PITCH + r];
            al[f][3] = A2l[(k0 + q + 4) * K3_PITCH + r + 8];
        }
#pragma unroll
        for (int nf = 0; nf < 8; nf++) {
            int n = nb0 + nf * 8 + g;
            bh[nf][0] = B2h[(k0 + q) * K3_PITCH + n];
            bh[nf][1] = B2h[(k0 + q + 4) * K3_PITCH + n];
            bl[nf][0] = B2l[(k0 + q) * K3_PITCH + n];
            bl[nf][1] = B2l[(k0 + q + 4) * K3_PITCH + n];
        }
#pragma unroll
        for (int f = 0; f < 2; f++)
#pragma unroll
            for (int nf = 0; nf < 8; nf++) {
                mma16816(acc[f][nf], ah[f], bh[nf]);
                mma16816(acc[f][nf], ah[f], bl[nf]);
                mma16816(acc[f][nf], al[f], bh[nf]);
            }
    }

    // ---- epilogue: bias + store (float2, cols 2q/2q+1 contiguous) ----
#pragma unroll
    for (int f = 0; f < 2; f++) {
        int r0 = m0 + f * 16 + g;
        float bias0 = __ldg(b_out + r0);
        float bias1 = __ldg(b_out + r0 + 8);
        float* o0 = out + ((size_t)b * CDIM + r0) * NSP + n0;
        float* o1 = o0 + 8 * NSP;
#pragma unroll
        for (int nf = 0; nf < 8; nf++) {
            int nc = nb0 + nf * 8 + q * 2;
            float2 v0 = {acc[f][nf][0] + bias0, acc[f][nf][1] + bias0};
            float2 v1 = {acc[f][nf][2] + bias1, acc[f][nf][3] + bias1};
            *(float2*)(o0 + nc) = v0;
            *(float2*)(o1 + nc) = v1;
        }
    }
}

// ---------------------------------------------------------------------------
extern "C" void kernel_launch(void* const* d_in, const int* in_sizes, int n_in,
                              void* d_out, int out_size) {
    const float* x     = (const float*)d_in[0];
    const float* w_qkv = (const float*)d_in[1];
    const float* w_out = (const float*)d_in[2];
    const float* b_out = (const float*)d_in[3];
    float* out = (float*)d_out;

    cudaFuncSetAttribute(k1_ctx, cudaFuncAttributeMaxDynamicSharedMemorySize,
                         SM1_FLOATS * sizeof(float));
    cudaFuncSetAttribute(k3_mm, cudaFuncAttributeMaxDynamicSharedMemorySize,
                         K3_SMEM_BYTES);

    k1_ctx<<<dim3(NCHUNKS, BATCH), 256, SM1_FLOATS * sizeof(float)>>>(x, w_qkv);
    k2_ctx<<<256, 256>>>();
    k2_u<<<1024, 256>>>(w_out);
    k2_m<<<1024, 256>>>(w_qkv);
    k3_mm<<<dim3(NSP / 128, BATCH), 256, K3_SMEM_BYTES>>>(x, b_out, out);
}